// round 2
// baseline (speedup 1.0000x reference)
#include <cuda_runtime.h>
#include <cstddef>

// Problem dims (fixed)
#define S_ROWS  8192      // B*L = 16*512
#define D_MODEL 512
#define D_HALF  256
#define G4      2048      // 4*D_MODEL

// ---------------------------------------------------------------------------
// Scratch (static device arrays — no runtime allocation)
// ---------------------------------------------------------------------------
__device__ float g_glu[S_ROWS * D_HALF];                    //  8 MB
__device__ float g_y[S_ROWS * D_MODEL];                     // 16 MB
__device__ float g_z[(size_t)S_ROWS * G4];                  // 64 MB
__device__ float g_gates[(size_t)S_ROWS * G4];              // 64 MB
__device__ float g_h[S_ROWS * D_MODEL];                     // 16 MB
__device__ float g_c[S_ROWS * D_MODEL];                     // 16 MB

// ---------------------------------------------------------------------------
// GLU: out[s, c] = a * sigmoid(b),  a = x[s, c], b = x[s, 256 + c]
// ---------------------------------------------------------------------------
__global__ void glu_kernel(const float* __restrict__ x, float* __restrict__ out)
{
    int idx = blockIdx.x * blockDim.x + threadIdx.x;     // float4 index
    if (idx >= S_ROWS * D_HALF / 4) return;
    int row = idx / (D_HALF / 4);
    int c4  = (idx % (D_HALF / 4)) * 4;
    const float* xr = x + (size_t)row * D_MODEL;
    float4 a = *(const float4*)(xr + c4);
    float4 b = *(const float4*)(xr + D_HALF + c4);
    float4 o;
    o.x = a.x / (1.f + __expf(-b.x));
    o.y = a.y / (1.f + __expf(-b.y));
    o.z = a.z / (1.f + __expf(-b.z));
    o.w = a.w / (1.f + __expf(-b.w));
    *(float4*)(out + (size_t)row * D_HALF + c4) = o;
}

// ---------------------------------------------------------------------------
// GEMM (TN, both operands K-major): C[m,n] = sum_k A[m*K+k] * Bw[n*K+k] (+bias)
// Tiles: 128x128x16, 256 threads, 8x8 per-thread micro-tile.
// All dims are multiples of the tile sizes (no bounds checks).
// ---------------------------------------------------------------------------
#define BM 128
#define BN 128
#define BK 16

__global__ __launch_bounds__(256, 2)
void gemm_tn_bias(const float* __restrict__ A, const float* __restrict__ Bw,
                  float* __restrict__ C, int M, int N, int K,
                  const float* __restrict__ bias0, const float* __restrict__ bias1)
{
    __shared__ float As[BK][BM + 4];
    __shared__ float Bs[BK][BN + 4];

    const int bm  = blockIdx.y * BM;
    const int bn  = blockIdx.x * BN;
    const int tid = threadIdx.x;
    const int tx  = tid & 15;       // 16 thread cols
    const int ty  = tid >> 4;       // 16 thread rows

    const int lrow = tid >> 2;           // 0..63
    const int lk   = (tid & 3) << 2;     // 0,4,8,12

    float acc[8][8];
    #pragma unroll
    for (int i = 0; i < 8; i++)
        #pragma unroll
        for (int j = 0; j < 8; j++) acc[i][j] = 0.f;

    const float* Aptr = A  + (size_t)(bm + lrow) * K + lk;
    const float* Bptr = Bw + (size_t)(bn + lrow) * K + lk;

    for (int k0 = 0; k0 < K; k0 += BK) {
        #pragma unroll
        for (int r = 0; r < 2; r++) {
            float4 v = *(const float4*)(Aptr + (size_t)(r * 64) * K + k0);
            int row = lrow + r * 64;
            As[lk + 0][row] = v.x; As[lk + 1][row] = v.y;
            As[lk + 2][row] = v.z; As[lk + 3][row] = v.w;
        }
        #pragma unroll
        for (int r = 0; r < 2; r++) {
            float4 v = *(const float4*)(Bptr + (size_t)(r * 64) * K + k0);
            int row = lrow + r * 64;
            Bs[lk + 0][row] = v.x; Bs[lk + 1][row] = v.y;
            Bs[lk + 2][row] = v.z; Bs[lk + 3][row] = v.w;
        }
        __syncthreads();

        #pragma unroll
        for (int kk = 0; kk < BK; kk++) {
            float af[8], bf[8];
            #pragma unroll
            for (int i = 0; i < 8; i++) af[i] = As[kk][ty * 8 + i];
            #pragma unroll
            for (int j = 0; j < 8; j++) bf[j] = Bs[kk][tx * 8 + j];
            #pragma unroll
            for (int i = 0; i < 8; i++)
                #pragma unroll
                for (int j = 0; j < 8; j++) acc[i][j] += af[i] * bf[j];
        }
        __syncthreads();
    }

    float bias[8];
    #pragma unroll
    for (int j = 0; j < 8; j++) {
        int n = bn + tx * 8 + j;
        float b = 0.f;
        if (bias0) b += bias0[n];
        if (bias1) b += bias1[n];
        bias[j] = b;
    }
    #pragma unroll
    for (int i = 0; i < 8; i++) {
        float* crow = C + (size_t)(bm + ty * 8 + i) * N + bn + tx * 8;
        float4 v0, v1;
        v0.x = acc[i][0] + bias[0]; v0.y = acc[i][1] + bias[1];
        v0.z = acc[i][2] + bias[2]; v0.w = acc[i][3] + bias[3];
        v1.x = acc[i][4] + bias[4]; v1.y = acc[i][5] + bias[5];
        v1.z = acc[i][6] + bias[6]; v1.w = acc[i][7] + bias[7];
        ((float4*)crow)[0] = v0;
        ((float4*)crow)[1] = v1;
    }
}

// ---------------------------------------------------------------------------
// LSTM pointwise step.
// For sequence s = b*512 + l at window step `step` (0..8), the input gates come
// from z-row (s - 8 + step) when l-8+step >= 0, otherwise from bias only
// (zero-padded input). gmm == nullptr marks step 0 (h = c = 0, no recurrence).
// ---------------------------------------------------------------------------
__global__ void lstm_step_kernel(const float* __restrict__ z,
                                 const float* __restrict__ gmm,
                                 const float* __restrict__ b_ih,
                                 const float* __restrict__ b_hh,
                                 const float* __restrict__ c_in,
                                 float* __restrict__ c_out,
                                 float* __restrict__ h_out,
                                 int step)
{
    int idx = blockIdx.x * blockDim.x + threadIdx.x;    // s*512 + d
    if (idx >= S_ROWS * D_MODEL) return;
    int s = idx >> 9;
    int d = idx & 511;
    int l = s & 511;
    int t = l - 8 + step;

    float gi, gf, gg, go;
    if (t >= 0) {
        const float* zr = z + (size_t)(s - 8 + step) * G4;   // row b*512 + t
        gi = zr[d];
        gf = zr[512 + d];
        gg = zr[1024 + d];
        go = zr[1536 + d];
    } else {
        gi = b_ih[d]        + b_hh[d];
        gf = b_ih[512 + d]  + b_hh[512 + d];
        gg = b_ih[1024 + d] + b_hh[1024 + d];
        go = b_ih[1536 + d] + b_hh[1536 + d];
    }

    float c_prev = 0.f;
    if (gmm) {
        const float* gr = gmm + (size_t)s * G4;
        gi += gr[d];
        gf += gr[512 + d];
        gg += gr[1024 + d];
        go += gr[1536 + d];
        c_prev = c_in[idx];
    }

    float si = 1.f / (1.f + __expf(-gi));
    float sf = 1.f / (1.f + __expf(-gf));
    float so = 1.f / (1.f + __expf(-go));
    float tg = tanhf(gg);
    float cn = sf * c_prev + si * tg;
    float hn = so * tanhf(cn);
    c_out[idx] = cn;
    h_out[idx] = hn;
}

// ---------------------------------------------------------------------------
// Launcher
// ---------------------------------------------------------------------------
extern "C" void kernel_launch(void* const* d_in, const int* in_sizes, int n_in,
                              void* d_out, int out_size)
{
    const float* x      = (const float*)d_in[0];
    const float* conv_w = (const float*)d_in[1];
    const float* conv_b = (const float*)d_in[2];
    const float* w_ih   = (const float*)d_in[3];
    const float* w_hh   = (const float*)d_in[4];
    const float* b_ih   = (const float*)d_in[5];
    const float* b_hh   = (const float*)d_in[6];
    float* out = (float*)d_out;

    float *glu, *y, *z, *gates, *h, *c;
    cudaGetSymbolAddress((void**)&glu,   g_glu);
    cudaGetSymbolAddress((void**)&y,     g_y);
    cudaGetSymbolAddress((void**)&z,     g_z);
    cudaGetSymbolAddress((void**)&gates, g_gates);
    cudaGetSymbolAddress((void**)&h,     g_h);
    cudaGetSymbolAddress((void**)&c,     g_c);

    // 1. GLU: x (8192 x 512) -> glu (8192 x 256)
    glu_kernel<<<(S_ROWS * D_HALF / 4 + 255) / 256, 256>>>(x, glu);

    // 2. conv projection: y = glu @ conv_w^T + conv_b   (8192 x 512, K=256)
    gemm_tn_bias<<<dim3(D_MODEL / BN, S_ROWS / BM), 256>>>(
        glu, conv_w, y, S_ROWS, D_MODEL, D_HALF, conv_b, nullptr);

    // 3. input projection (shared across all 9 window steps):
    //    z = y @ w_ih^T + b_ih + b_hh   (8192 x 2048, K=512)
    gemm_tn_bias<<<dim3(G4 / BN, S_ROWS / BM), 256>>>(
        y, w_ih, z, S_ROWS, G4, D_MODEL, b_ih, b_hh);

    const int pw_blocks = (S_ROWS * D_MODEL + 255) / 256;

    // 4. step 0: h = c = 0 -> pointwise only
    lstm_step_kernel<<<pw_blocks, 256>>>(z, nullptr, b_ih, b_hh, c, c, h, 0);

    // 5. steps 1..8: gates = h @ w_hh^T, then pointwise update
    for (int k = 1; k <= 8; k++) {
        gemm_tn_bias<<<dim3(G4 / BN, S_ROWS / BM), 256>>>(
            h, w_hh, gates, S_ROWS, G4, D_MODEL, nullptr, nullptr);
        float* h_out = (k == 8) ? out : h;
        lstm_step_kernel<<<pw_blocks, 256>>>(z, gates, b_ih, b_hh, c, c, h_out, k);
    }
}

// round 4
// speedup vs baseline: 1.9763x; 1.9763x over previous
#include <cuda_runtime.h>
#include <cstdint>
#include <cstddef>

// Problem dims (fixed)
#define S_ROWS  8192      // B*L = 16*512
#define D_MODEL 512
#define D_HALF  256
#define G4      2048      // 4*D_MODEL

// ---------------------------------------------------------------------------
// Scratch (static device arrays — no runtime allocation)
// ---------------------------------------------------------------------------
__device__ float g_glu[S_ROWS * D_HALF];
__device__ float g_y[S_ROWS * D_MODEL];
__device__ float g_z[(size_t)S_ROWS * G4];
__device__ float g_gates[(size_t)S_ROWS * G4];
__device__ float g_h[S_ROWS * D_MODEL];
__device__ float g_c[S_ROWS * D_MODEL];
__device__ float g_wih_r[G4 * D_MODEL];     // tf32-rounded weights
__device__ float g_whh_r[G4 * D_MODEL];
__device__ float g_convw_r[D_MODEL * D_HALF];

// ---------------------------------------------------------------------------
// Helpers (base PTX only — NO sm_103a-gated instructions)
// ---------------------------------------------------------------------------
__device__ __forceinline__ uint32_t smem_u32(const void* p) {
    uint32_t a;
    asm("{ .reg .u64 t; cvta.to.shared.u64 t, %1; cvt.u32.u64 %0, t; }" : "=r"(a) : "l"(p));
    return a;
}
__device__ __forceinline__ float tf32r(float x) {
    uint32_t u;
    asm("cvt.rna.tf32.f32 %0, %1;" : "=r"(u) : "f"(x));
    return __uint_as_float(u);
}
__device__ __forceinline__ void cp16(uint32_t dst, const void* src) {
    asm volatile("cp.async.cg.shared.global [%0], [%1], 16;" :: "r"(dst), "l"(src) : "memory");
}
__device__ __forceinline__ void cp_commit() {
    asm volatile("cp.async.commit_group;" ::: "memory");
}
template <int N>
__device__ __forceinline__ void cp_wait() {
    asm volatile("cp.async.wait_group %0;" :: "n"(N) : "memory");
}

// m16n8k8 tf32 MMA: D = A*B + D
__device__ __forceinline__ void mma_tf32(float c[4], const uint32_t a[4], const uint32_t b[2]) {
    asm volatile(
        "mma.sync.aligned.m16n8k8.row.col.f32.tf32.tf32.f32 "
        "{%0,%1,%2,%3}, {%4,%5,%6,%7}, {%8,%9}, {%0,%1,%2,%3};"
        : "+f"(c[0]), "+f"(c[1]), "+f"(c[2]), "+f"(c[3])
        : "r"(a[0]), "r"(a[1]), "r"(a[2]), "r"(a[3]), "r"(b[0]), "r"(b[1]));
}

// ---------------------------------------------------------------------------
// Tensor-core GEMM (TN): C[m,n] = sum_k A[m*K+k] * Bw[n*K+k] (+bias0+bias1)
// Block 128x128, 4 warps (2x2), warp tile 64x64, BK=32, 2-stage cp.async.
// All dims multiples of tile sizes (no bounds checks).
// ---------------------------------------------------------------------------
#define BM 128
#define BN 128
#define BK 32
#define ROWF 36                      // 32 + 4 pad floats per smem row
#define STAGE_F ((BM + BN) * ROWF)   // 9216 floats per stage
#define GEMM_SMEM (2 * STAGE_F * 4)  // 73728 bytes

__global__ __launch_bounds__(128, 2)
void gemm_mma(const float* __restrict__ A, const float* __restrict__ Bw,
              float* __restrict__ C, int Nt, int K,
              const float* __restrict__ bias0, const float* __restrict__ bias1,
              int round_out)
{
    extern __shared__ float sm[];
    const int tid  = threadIdx.x;
    const int lane = tid & 31;
    const int wid  = tid >> 5;
    const int g    = lane >> 2;      // group id (0..7)
    const int ctg  = lane & 3;       // thread in group (0..3)
    const int wm   = (wid & 1) * 64; // warp row base within block
    const int wn   = (wid >> 1) * 64;
    const int bm   = blockIdx.y * BM;
    const int bn   = blockIdx.x * BN;
    const int KT   = K / BK;

    const uint32_t smem_base = smem_u32(sm);

    // ---- stage loader: K-panel kt into buffer s ----
    auto load_stage = [&](int kt, int s) {
        const int k0 = kt * BK;
        const uint32_t abase = smem_base + (uint32_t)s * STAGE_F * 4;
        const uint32_t bbase = abase + BM * ROWF * 4;
        #pragma unroll
        for (int i = 0; i < 8; i++) {           // A: 128 rows x 8 float4
            int idx = tid + i * 128;
            int r = idx >> 3, c = idx & 7;
            cp16(abase + (uint32_t)(r * ROWF + c * 4) * 4,
                 A + (size_t)(bm + r) * K + k0 + c * 4);
        }
        #pragma unroll
        for (int i = 0; i < 8; i++) {           // B: 128 rows x 8 float4
            int idx = tid + i * 128;
            int r = idx >> 3, c = idx & 7;
            cp16(bbase + (uint32_t)(r * ROWF + c * 4) * 4,
                 Bw + (size_t)(bn + r) * K + k0 + c * 4);
        }
    };

    float acc[4][8][4];
    #pragma unroll
    for (int mi = 0; mi < 4; mi++)
        #pragma unroll
        for (int ni = 0; ni < 8; ni++)
            #pragma unroll
            for (int t = 0; t < 4; t++) acc[mi][ni][t] = 0.f;

    load_stage(0, 0);
    cp_commit();

    for (int kt = 0; kt < KT; kt++) {
        if (kt + 1 < KT) {
            load_stage(kt + 1, (kt + 1) & 1);
            cp_commit();
            cp_wait<1>();
        } else {
            cp_wait<0>();
        }
        __syncthreads();

        const float* As = sm + (kt & 1) * STAGE_F;
        const float* Bs = As + BM * ROWF;

        #pragma unroll
        for (int ks = 0; ks < 4; ks++) {
            uint32_t af[4][4], bf[8][2];
            #pragma unroll
            for (int mi = 0; mi < 4; mi++) {
                const float* p = As + (wm + mi * 16 + g) * ROWF + ks * 8 + ctg;
                af[mi][0] = *(const uint32_t*)(p);
                af[mi][1] = *(const uint32_t*)(p + 8 * ROWF);
                af[mi][2] = *(const uint32_t*)(p + 4);
                af[mi][3] = *(const uint32_t*)(p + 8 * ROWF + 4);
            }
            #pragma unroll
            for (int ni = 0; ni < 8; ni++) {
                const float* q = Bs + (wn + ni * 8 + g) * ROWF + ks * 8 + ctg;
                bf[ni][0] = *(const uint32_t*)(q);
                bf[ni][1] = *(const uint32_t*)(q + 4);
            }
            #pragma unroll
            for (int mi = 0; mi < 4; mi++)
                #pragma unroll
                for (int ni = 0; ni < 8; ni++)
                    mma_tf32(acc[mi][ni], af[mi], bf[ni]);
        }
        __syncthreads();
    }

    // ---- epilogue: bias + optional tf32 rounding, float2 stores ----
    #pragma unroll
    for (int ni = 0; ni < 8; ni++) {
        const int col = bn + wn + ni * 8 + 2 * ctg;
        float b0 = 0.f, b1 = 0.f;
        if (bias0) { b0 += bias0[col]; b1 += bias0[col + 1]; }
        if (bias1) { b0 += bias1[col]; b1 += bias1[col + 1]; }
        #pragma unroll
        for (int mi = 0; mi < 4; mi++) {
            const int row = bm + wm + mi * 16 + g;
            float v0 = acc[mi][ni][0] + b0;
            float v1 = acc[mi][ni][1] + b1;
            float v2 = acc[mi][ni][2] + b0;
            float v3 = acc[mi][ni][3] + b1;
            if (round_out) {
                v0 = tf32r(v0); v1 = tf32r(v1); v2 = tf32r(v2); v3 = tf32r(v3);
            }
            *(float2*)(C + (size_t)row * Nt + col)       = make_float2(v0, v1);
            *(float2*)(C + (size_t)(row + 8) * Nt + col) = make_float2(v2, v3);
        }
    }
}

// ---------------------------------------------------------------------------
// Elementwise: round fp32 -> tf32 (for GEMM weight operands)
// ---------------------------------------------------------------------------
__global__ void round_kernel(const float* __restrict__ src, float* __restrict__ dst, int n4)
{
    int i = blockIdx.x * blockDim.x + threadIdx.x;
    if (i >= n4) return;
    float4 v = ((const float4*)src)[i];
    v.x = tf32r(v.x); v.y = tf32r(v.y); v.z = tf32r(v.z); v.w = tf32r(v.w);
    ((float4*)dst)[i] = v;
}

// ---------------------------------------------------------------------------
// GLU: out[s,c] = a * sigmoid(b); output rounded to tf32 (feeds conv GEMM)
// ---------------------------------------------------------------------------
__global__ void glu_kernel(const float* __restrict__ x, float* __restrict__ out)
{
    int idx = blockIdx.x * blockDim.x + threadIdx.x;
    if (idx >= S_ROWS * D_HALF / 4) return;
    int row = idx / (D_HALF / 4);
    int c4  = (idx % (D_HALF / 4)) * 4;
    const float* xr = x + (size_t)row * D_MODEL;
    float4 a = *(const float4*)(xr + c4);
    float4 b = *(const float4*)(xr + D_HALF + c4);
    float4 o;
    o.x = tf32r(a.x / (1.f + __expf(-b.x)));
    o.y = tf32r(a.y / (1.f + __expf(-b.y)));
    o.z = tf32r(a.z / (1.f + __expf(-b.z)));
    o.w = tf32r(a.w / (1.f + __expf(-b.w)));
    *(float4*)(out + (size_t)row * D_HALF + c4) = o;
}

// ---------------------------------------------------------------------------
// LSTM pointwise step. round_h: round h output to tf32 (feeds next GEMM).
// ---------------------------------------------------------------------------
__global__ void lstm_step_kernel(const float* __restrict__ z,
                                 const float* __restrict__ gmm,
                                 const float* __restrict__ b_ih,
                                 const float* __restrict__ b_hh,
                                 const float* __restrict__ c_in,
                                 float* __restrict__ c_out,
                                 float* __restrict__ h_out,
                                 int step, int round_h)
{
    int idx = blockIdx.x * blockDim.x + threadIdx.x;
    if (idx >= S_ROWS * D_MODEL) return;
    int s = idx >> 9;
    int d = idx & 511;
    int l = s & 511;
    int t = l - 8 + step;

    float gi, gf, gg, go;
    if (t >= 0) {
        const float* zr = z + (size_t)(s - 8 + step) * G4;
        gi = zr[d];
        gf = zr[512 + d];
        gg = zr[1024 + d];
        go = zr[1536 + d];
    } else {
        gi = b_ih[d]        + b_hh[d];
        gf = b_ih[512 + d]  + b_hh[512 + d];
        gg = b_ih[1024 + d] + b_hh[1024 + d];
        go = b_ih[1536 + d] + b_hh[1536 + d];
    }

    float c_prev = 0.f;
    if (gmm) {
        const float* gr = gmm + (size_t)s * G4;
        gi += gr[d];
        gf += gr[512 + d];
        gg += gr[1024 + d];
        go += gr[1536 + d];
        c_prev = c_in[idx];
    }

    float si = 1.f / (1.f + __expf(-gi));
    float sf = 1.f / (1.f + __expf(-gf));
    float so = 1.f / (1.f + __expf(-go));
    float tg = tanhf(gg);
    float cn = sf * c_prev + si * tg;
    float hn = so * tanhf(cn);
    c_out[idx] = cn;
    h_out[idx] = round_h ? tf32r(hn) : hn;
}

// ---------------------------------------------------------------------------
// Launcher
// ---------------------------------------------------------------------------
extern "C" void kernel_launch(void* const* d_in, const int* in_sizes, int n_in,
                              void* d_out, int out_size)
{
    const float* x      = (const float*)d_in[0];
    const float* conv_w = (const float*)d_in[1];
    const float* conv_b = (const float*)d_in[2];
    const float* w_ih   = (const float*)d_in[3];
    const float* w_hh   = (const float*)d_in[4];
    const float* b_ih   = (const float*)d_in[5];
    const float* b_hh   = (const float*)d_in[6];
    float* out = (float*)d_out;

    float *glu, *y, *z, *gates, *h, *c, *wihr, *whhr, *convwr;
    cudaGetSymbolAddress((void**)&glu,    g_glu);
    cudaGetSymbolAddress((void**)&y,      g_y);
    cudaGetSymbolAddress((void**)&z,      g_z);
    cudaGetSymbolAddress((void**)&gates,  g_gates);
    cudaGetSymbolAddress((void**)&h,      g_h);
    cudaGetSymbolAddress((void**)&c,      g_c);
    cudaGetSymbolAddress((void**)&wihr,   g_wih_r);
    cudaGetSymbolAddress((void**)&whhr,   g_whh_r);
    cudaGetSymbolAddress((void**)&convwr, g_convw_r);

    static int smem_set = 0;
    if (!smem_set) {
        cudaFuncSetAttribute(gemm_mma, cudaFuncAttributeMaxDynamicSharedMemorySize, GEMM_SMEM);
        smem_set = 1;
    }

    // 0. round weights to tf32 once per launch
    round_kernel<<<(G4 * D_MODEL / 4 + 255) / 256, 256>>>(w_ih, wihr, G4 * D_MODEL / 4);
    round_kernel<<<(G4 * D_MODEL / 4 + 255) / 256, 256>>>(w_hh, whhr, G4 * D_MODEL / 4);
    round_kernel<<<(D_MODEL * D_HALF / 4 + 255) / 256, 256>>>(conv_w, convwr, D_MODEL * D_HALF / 4);

    // 1. GLU (rounded output)
    glu_kernel<<<(S_ROWS * D_HALF / 4 + 255) / 256, 256>>>(x, glu);

    // 2. conv projection: y = glu @ conv_w^T + conv_b  (8192 x 512, K=256), round y
    gemm_mma<<<dim3(D_MODEL / BN, S_ROWS / BM), 128, GEMM_SMEM>>>(
        glu, convwr, y, D_MODEL, D_HALF, conv_b, nullptr, 1);

    // 3. z = y @ w_ih^T + b_ih + b_hh   (8192 x 2048, K=512)
    gemm_mma<<<dim3(G4 / BN, S_ROWS / BM), 128, GEMM_SMEM>>>(
        y, wihr, z, G4, D_MODEL, b_ih, b_hh, 0);

    const int pw_blocks = (S_ROWS * D_MODEL + 255) / 256;

    // 4. step 0: pointwise only (h = c = 0)
    lstm_step_kernel<<<pw_blocks, 256>>>(z, nullptr, b_ih, b_hh, c, c, h, 0, 1);

    // 5. steps 1..8
    for (int k = 1; k <= 8; k++) {
        gemm_mma<<<dim3(G4 / BN, S_ROWS / BM), 128, GEMM_SMEM>>>(
            h, whhr, gates, G4, D_MODEL, nullptr, nullptr, 0);
        float* h_out = (k == 8) ? out : h;
        lstm_step_kernel<<<pw_blocks, 256>>>(z, gates, b_ih, b_hh, c, c, h_out, k,
                                             (k < 8) ? 1 : 0);
    }
}

// round 6
// speedup vs baseline: 2.0068x; 1.0155x over previous
#include <cuda_runtime.h>
#include <cstdint>
#include <cstddef>

// Problem dims (fixed)
#define S_ROWS  8192      // B*L = 16*512
#define D_MODEL 512
#define D_HALF  256
#define G4      2048      // 4*D_MODEL

// ---------------------------------------------------------------------------
// Scratch (static device arrays — no runtime allocation)
// ---------------------------------------------------------------------------
__device__ float g_glu[S_ROWS * D_HALF];
__device__ float g_y[S_ROWS * D_MODEL];
__device__ float g_z[(size_t)S_ROWS * G4];      // gate-interleaved cols: n' = 4d+g
__device__ float g_h0[S_ROWS * D_MODEL];        // ping-pong h buffers (fixes WAR race)
__device__ float g_h1[S_ROWS * D_MODEL];
__device__ float g_c[S_ROWS * D_MODEL];
__device__ float g_wih_p[G4 * D_MODEL];         // permuted + tf32-rounded
__device__ float g_whh_p[G4 * D_MODEL];         // permuted + tf32-rounded
__device__ float g_convw_r[D_MODEL * D_HALF];   // tf32-rounded
__device__ float g_bsum[G4];                    // b_ih + b_hh, permuted

// ---------------------------------------------------------------------------
// Helpers (base PTX only — tcgen05 is sm_103a-gated and unavailable here)
// ---------------------------------------------------------------------------
__device__ __forceinline__ uint32_t smem_u32(const void* p) {
    uint32_t a;
    asm("{ .reg .u64 t; cvta.to.shared.u64 t, %1; cvt.u32.u64 %0, t; }" : "=r"(a) : "l"(p));
    return a;
}
__device__ __forceinline__ float tf32r(float x) {
    uint32_t u;
    asm("cvt.rna.tf32.f32 %0, %1;" : "=r"(u) : "f"(x));
    return __uint_as_float(u);
}
__device__ __forceinline__ void cp16(uint32_t dst, const void* src) {
    asm volatile("cp.async.cg.shared.global [%0], [%1], 16;" :: "r"(dst), "l"(src) : "memory");
}
__device__ __forceinline__ void cp_commit() {
    asm volatile("cp.async.commit_group;" ::: "memory");
}
template <int N>
__device__ __forceinline__ void cp_wait() {
    asm volatile("cp.async.wait_group %0;" :: "n"(N) : "memory");
}

// m16n8k8 tf32 MMA: D = A*B + D
__device__ __forceinline__ void mma_tf32(float c[4], const uint32_t a[4], const uint32_t b[2]) {
    asm volatile(
        "mma.sync.aligned.m16n8k8.row.col.f32.tf32.tf32.f32 "
        "{%0,%1,%2,%3}, {%4,%5,%6,%7}, {%8,%9}, {%0,%1,%2,%3};"
        : "+f"(c[0]), "+f"(c[1]), "+f"(c[2]), "+f"(c[3])
        : "r"(a[0]), "r"(a[1]), "r"(a[2]), "r"(a[3]), "r"(b[0]), "r"(b[1]));
}

__device__ __forceinline__ float sigm(float x) { return 1.f / (1.f + __expf(-x)); }

// ---------------------------------------------------------------------------
// Tensor-core GEMM (TN): C[m,n] = sum_k A[m*K+k] * Bw[n*K+k] (+bias)
// Block BMT x 128, 8 warps, warp tile 64 x (128*64/BMT), BK=32, 3-stage cp.async.
// Fused-LSTM mode (z != nullptr): epilogue applies LSTM cell, writes h & c,
// never touches C. Requires gate-interleaved B/z layout (col n' = 4d + gate).
// h_out MUST NOT alias the A operand (ping-pong buffers in the launcher).
// ---------------------------------------------------------------------------
#define BK   32
#define ROWF 36                       // 32 + 4 pad floats per smem row
#define GTS  136                      // epilogue gate-tile row stride (floats)

template <int BMT>
__global__ __launch_bounds__(256, 1)
void gemm_mma(const float* __restrict__ A, const float* __restrict__ Bw,
              float* __restrict__ C, int Nt, int K,
              const float* __restrict__ bias, int round_out,
              const float* __restrict__ z, const float* __restrict__ bsum,
              const float* __restrict__ c_in, float* __restrict__ c_out,
              float* __restrict__ h_out, int step, int round_h, int write_c)
{
    constexpr int MW  = BMT / 64;       // warps along M
    constexpr int NW  = 8 / MW;         // warps along N
    constexpr int WNT = 128 / NW;       // warp N tile
    constexpr int NI  = WNT / 8;        // n-fragments per warp
    constexpr int STAGE_F = (BMT + 128) * ROWF;

    extern __shared__ float sm[];
    const int tid  = threadIdx.x;
    const int lane = tid & 31;
    const int wid  = tid >> 5;
    const int g    = lane >> 2;
    const int ctg  = lane & 3;
    const int wm   = (wid % MW) * 64;
    const int wn   = (wid / MW) * WNT;
    const int bm   = blockIdx.y * BMT;
    const int bn   = blockIdx.x * 128;
    const int KT   = K / BK;
    const uint32_t sb = smem_u32(sm);

    auto load_stage = [&](int kt, int s) {
        const int k0 = kt * BK;
        const uint32_t ab = sb + (uint32_t)s * STAGE_F * 4;
        const uint32_t bb = ab + BMT * ROWF * 4;
        #pragma unroll
        for (int i = 0; i < BMT / 32; i++) {            // A: BMT rows x 8 float4
            int idx = tid + i * 256;
            int r = idx >> 3, c = idx & 7;
            cp16(ab + (uint32_t)(r * ROWF + c * 4) * 4,
                 A + (size_t)(bm + r) * K + k0 + c * 4);
        }
        #pragma unroll
        for (int i = 0; i < 4; i++) {                   // B: 128 rows x 8 float4
            int idx = tid + i * 256;
            int r = idx >> 3, c = idx & 7;
            cp16(bb + (uint32_t)(r * ROWF + c * 4) * 4,
                 Bw + (size_t)(bn + r) * K + k0 + c * 4);
        }
    };

    float acc[4][NI][4];
    #pragma unroll
    for (int mi = 0; mi < 4; mi++)
        #pragma unroll
        for (int ni = 0; ni < NI; ni++)
            #pragma unroll
            for (int t = 0; t < 4; t++) acc[mi][ni][t] = 0.f;

    // prologue: 2 stages in flight
    load_stage(0, 0); cp_commit();
    load_stage(1, 1); cp_commit();

    for (int kt = 0; kt < KT; kt++) {
        if (kt + 2 < KT) load_stage(kt + 2, (kt + 2) % 3);
        cp_commit();                    // commit (possibly empty) keeps group count uniform
        cp_wait<2>();                   // stage kt complete
        __syncthreads();

        const float* As = sm + (kt % 3) * STAGE_F;
        const float* Bs = As + BMT * ROWF;

        #pragma unroll
        for (int ks = 0; ks < 4; ks++) {
            uint32_t af[4][4], bf[NI][2];
            #pragma unroll
            for (int mi = 0; mi < 4; mi++) {
                const float* p = As + (wm + mi * 16 + g) * ROWF + ks * 8 + ctg;
                af[mi][0] = *(const uint32_t*)(p);
                af[mi][1] = *(const uint32_t*)(p + 8 * ROWF);
                af[mi][2] = *(const uint32_t*)(p + 4);
                af[mi][3] = *(const uint32_t*)(p + 8 * ROWF + 4);
            }
            #pragma unroll
            for (int ni = 0; ni < NI; ni++) {
                const float* q = Bs + (wn + ni * 8 + g) * ROWF + ks * 8 + ctg;
                bf[ni][0] = *(const uint32_t*)(q);
                bf[ni][1] = *(const uint32_t*)(q + 4);
            }
            #pragma unroll
            for (int mi = 0; mi < 4; mi++)
                #pragma unroll
                for (int ni = 0; ni < NI; ni++)
                    mma_tf32(acc[mi][ni], af[mi], bf[ni]);
        }
        __syncthreads();
    }

    if (!z) {
        // ---- plain epilogue: bias + optional tf32 rounding ----
        #pragma unroll
        for (int ni = 0; ni < NI; ni++) {
            const int col = bn + wn + ni * 8 + 2 * ctg;
            float b0 = 0.f, b1 = 0.f;
            if (bias) { b0 = bias[col]; b1 = bias[col + 1]; }
            #pragma unroll
            for (int mi = 0; mi < 4; mi++) {
                const int row = bm + wm + mi * 16 + g;
                float v0 = acc[mi][ni][0] + b0;
                float v1 = acc[mi][ni][1] + b1;
                float v2 = acc[mi][ni][2] + b0;
                float v3 = acc[mi][ni][3] + b1;
                if (round_out) { v0 = tf32r(v0); v1 = tf32r(v1); v2 = tf32r(v2); v3 = tf32r(v3); }
                *(float2*)(C + (size_t)row * Nt + col)       = make_float2(v0, v1);
                *(float2*)(C + (size_t)(row + 8) * Nt + col) = make_float2(v2, v3);
            }
        }
    } else {
        // ---- fused LSTM epilogue ----
        // 1. accumulators -> smem gate tile [BMT][128] (stride GTS, 16B-aligned rows)
        #pragma unroll
        for (int ni = 0; ni < NI; ni++) {
            const int cl = wn + ni * 8 + 2 * ctg;
            #pragma unroll
            for (int mi = 0; mi < 4; mi++) {
                const int rl = wm + mi * 16 + g;
                *(float2*)(sm + (size_t)rl * GTS + cl)       = make_float2(acc[mi][ni][0], acc[mi][ni][1]);
                *(float2*)(sm + (size_t)(rl + 8) * GTS + cl) = make_float2(acc[mi][ni][2], acc[mi][ni][3]);
            }
        }
        __syncthreads();

        // 2. pointwise LSTM cell over (row, d) items
        const int dn0 = bn >> 2;                     // 32 hidden units per N tile
        #pragma unroll
        for (int it = 0; it < BMT / 8; it++) {
            int idx = it * 256 + tid;
            int rl = idx >> 5, dl = idx & 31;
            int s = bm + rl, d = dn0 + dl;
            int l = s & 511, t = l - 8 + step;

            float4 gz;
            if (t >= 0) gz = *(const float4*)(z + (size_t)(s - 8 + step) * G4 + 4 * d);
            else        gz = *(const float4*)(bsum + 4 * d);

            float4 gr = *(const float4*)(sm + (size_t)rl * GTS + 4 * dl);
            float gi = gz.x + gr.x;
            float gf = gz.y + gr.y;
            float gg = gz.z + gr.z;
            float go = gz.w + gr.w;

            float c_prev = c_in[(size_t)s * D_MODEL + d];
            float cn = sigm(gf) * c_prev + sigm(gi) * tanhf(gg);
            float hn = sigm(go) * tanhf(cn);
            if (write_c) c_out[(size_t)s * D_MODEL + d] = cn;
            h_out[(size_t)s * D_MODEL + d] = round_h ? tf32r(hn) : hn;
        }
    }
}

// ---------------------------------------------------------------------------
// Weight permute + tf32 round: dst[(4d+g), k] = rna(src[(g*512+d), k])
// ---------------------------------------------------------------------------
__global__ void permute_round_w(const float* __restrict__ src, float* __restrict__ dst)
{
    int i = blockIdx.x * blockDim.x + threadIdx.x;      // float4 index
    if (i >= G4 * D_MODEL / 4) return;
    int np = i >> 7;                // dst row (0..2047)
    int c4 = (i & 127) * 4;
    int d = np >> 2, gg = np & 3;
    float4 v = *(const float4*)(src + (size_t)(gg * D_MODEL + d) * D_MODEL + c4);
    v.x = tf32r(v.x); v.y = tf32r(v.y); v.z = tf32r(v.z); v.w = tf32r(v.w);
    *(float4*)(dst + (size_t)np * D_MODEL + c4) = v;
}

__global__ void round_kernel(const float* __restrict__ src, float* __restrict__ dst, int n4)
{
    int i = blockIdx.x * blockDim.x + threadIdx.x;
    if (i >= n4) return;
    float4 v = ((const float4*)src)[i];
    v.x = tf32r(v.x); v.y = tf32r(v.y); v.z = tf32r(v.z); v.w = tf32r(v.w);
    ((float4*)dst)[i] = v;
}

__global__ void bsum_kernel(const float* __restrict__ bih, const float* __restrict__ bhh,
                            float* __restrict__ bs)
{
    int np = blockIdx.x * blockDim.x + threadIdx.x;
    if (np >= G4) return;
    int d = np >> 2, gg = np & 3;
    bs[np] = bih[gg * D_MODEL + d] + bhh[gg * D_MODEL + d];
}

// ---------------------------------------------------------------------------
// GLU: out[s,c] = a * sigmoid(b); rounded to tf32 (feeds conv GEMM)
// ---------------------------------------------------------------------------
__global__ void glu_kernel(const float* __restrict__ x, float* __restrict__ out)
{
    int idx = blockIdx.x * blockDim.x + threadIdx.x;
    if (idx >= S_ROWS * D_HALF / 4) return;
    int row = idx / (D_HALF / 4);
    int c4  = (idx % (D_HALF / 4)) * 4;
    const float* xr = x + (size_t)row * D_MODEL;
    float4 a = *(const float4*)(xr + c4);
    float4 b = *(const float4*)(xr + D_HALF + c4);
    float4 o;
    o.x = tf32r(a.x * sigm(b.x));
    o.y = tf32r(a.y * sigm(b.y));
    o.z = tf32r(a.z * sigm(b.z));
    o.w = tf32r(a.w * sigm(b.w));
    *(float4*)(out + (size_t)row * D_HALF + c4) = o;
}

// ---------------------------------------------------------------------------
// LSTM step 0 (h = c = 0): pointwise from gate-interleaved z only.
// ---------------------------------------------------------------------------
__global__ void lstm_step0(const float* __restrict__ z, const float* __restrict__ bsum,
                           float* __restrict__ c_out, float* __restrict__ h_out)
{
    int idx = blockIdx.x * blockDim.x + threadIdx.x;    // s*512 + d
    if (idx >= S_ROWS * D_MODEL) return;
    int s = idx >> 9, d = idx & 511, l = s & 511;
    float4 gz = (l >= 8) ? *(const float4*)(z + (size_t)(s - 8) * G4 + 4 * d)
                         : *(const float4*)(bsum + 4 * d);
    float cn = sigm(gz.x) * tanhf(gz.z);
    float hn = sigm(gz.w) * tanhf(cn);
    c_out[idx] = cn;
    h_out[idx] = tf32r(hn);
}

// ---------------------------------------------------------------------------
// Launcher
// ---------------------------------------------------------------------------
extern "C" void kernel_launch(void* const* d_in, const int* in_sizes, int n_in,
                              void* d_out, int out_size)
{
    const float* x      = (const float*)d_in[0];
    const float* conv_w = (const float*)d_in[1];
    const float* conv_b = (const float*)d_in[2];
    const float* w_ih   = (const float*)d_in[3];
    const float* w_hh   = (const float*)d_in[4];
    const float* b_ih   = (const float*)d_in[5];
    const float* b_hh   = (const float*)d_in[6];
    float* out = (float*)d_out;

    float *glu, *y, *z, *h0, *h1, *c, *wihp, *whhp, *convwr, *bsum;
    cudaGetSymbolAddress((void**)&glu,    g_glu);
    cudaGetSymbolAddress((void**)&y,      g_y);
    cudaGetSymbolAddress((void**)&z,      g_z);
    cudaGetSymbolAddress((void**)&h0,     g_h0);
    cudaGetSymbolAddress((void**)&h1,     g_h1);
    cudaGetSymbolAddress((void**)&c,      g_c);
    cudaGetSymbolAddress((void**)&wihp,   g_wih_p);
    cudaGetSymbolAddress((void**)&whhp,   g_whh_p);
    cudaGetSymbolAddress((void**)&convwr, g_convw_r);
    cudaGetSymbolAddress((void**)&bsum,   g_bsum);

    constexpr int SMEM256 = 3 * (256 + 128) * ROWF * 4;   // 165888 B (>= epi 139264)
    constexpr int SMEM128 = 3 * (128 + 128) * ROWF * 4;   // 110592 B

    static int smem_set = 0;
    if (!smem_set) {
        cudaFuncSetAttribute(gemm_mma<256>, cudaFuncAttributeMaxDynamicSharedMemorySize, SMEM256);
        cudaFuncSetAttribute(gemm_mma<128>, cudaFuncAttributeMaxDynamicSharedMemorySize, SMEM128);
        smem_set = 1;
    }

    // 0. weight prep: permute + round recurrent weights, round conv, combine biases
    permute_round_w<<<(G4 * D_MODEL / 4 + 255) / 256, 256>>>(w_ih, wihp);
    permute_round_w<<<(G4 * D_MODEL / 4 + 255) / 256, 256>>>(w_hh, whhp);
    round_kernel<<<(D_MODEL * D_HALF / 4 + 255) / 256, 256>>>(conv_w, convwr, D_MODEL * D_HALF / 4);
    bsum_kernel<<<(G4 + 255) / 256, 256>>>(b_ih, b_hh, bsum);

    // 1. GLU (tf32-rounded output)
    glu_kernel<<<(S_ROWS * D_HALF / 4 + 255) / 256, 256>>>(x, glu);

    // 2. conv projection: y = glu @ conv_w^T + conv_b (8192x512, K=256), round y
    gemm_mma<128><<<dim3(D_MODEL / 128, S_ROWS / 128), 256, SMEM128>>>(
        glu, convwr, y, D_MODEL, D_HALF, conv_b, 1,
        nullptr, nullptr, nullptr, nullptr, nullptr, 0, 0, 0);

    // 3. z = y @ w_ih_p^T + bsum   (8192x2048, K=512, gate-interleaved cols)
    gemm_mma<256><<<dim3(G4 / 128, S_ROWS / 256), 256, SMEM256>>>(
        y, wihp, z, G4, D_MODEL, bsum, 0,
        nullptr, nullptr, nullptr, nullptr, nullptr, 0, 0, 0);

    // 4. step 0 pointwise (h = c = 0) -> h0
    lstm_step0<<<(S_ROWS * D_MODEL + 255) / 256, 256>>>(z, bsum, c, h0);

    // 5. steps 1..8: fused recurrent GEMM + LSTM cell, ping-pong h buffers
    float* hb[2] = {h0, h1};
    for (int k = 1; k <= 8; k++) {
        const float* h_in = hb[(k - 1) & 1];
        float* h_out = (k == 8) ? out : hb[k & 1];
        gemm_mma<256><<<dim3(G4 / 128, S_ROWS / 256), 256, SMEM256>>>(
            h_in, whhp, nullptr, G4, D_MODEL, nullptr, 0,
            z, bsum, c, c, h_out, k, (k < 8) ? 1 : 0, (k < 8) ? 1 : 0);
    }
}

// round 7
// speedup vs baseline: 2.9483x; 1.4691x over previous
#include <cuda_runtime.h>
#include <cstdint>
#include <cstddef>

// Problem dims (fixed)
#define S_ROWS  8192      // B*L = 16*512
#define D_MODEL 512
#define D_HALF  256
#define G4      2048      // 4*D_MODEL

// ---------------------------------------------------------------------------
// Scratch (static device arrays — no runtime allocation)
// ---------------------------------------------------------------------------
__device__ float g_glu[S_ROWS * D_HALF];
__device__ float g_y[S_ROWS * D_MODEL];
__device__ float g_z[(size_t)S_ROWS * G4];      // gate-interleaved cols: n' = 4d+g
__device__ float g_h0[S_ROWS * D_MODEL];        // ping-pong h buffers (no WAR race)
__device__ float g_h1[S_ROWS * D_MODEL];
__device__ float g_c[S_ROWS * D_MODEL];
__device__ float g_wih_p[G4 * D_MODEL];         // permuted + tf32-rounded
__device__ float g_whh_p[G4 * D_MODEL];         // permuted + tf32-rounded
__device__ float g_convw_r[D_MODEL * D_HALF];   // tf32-rounded
__device__ float g_bsum[G4];                    // b_ih + b_hh, permuted

// ---------------------------------------------------------------------------
// Helpers (base PTX only — tcgen05 is sm_103a-gated and unavailable here)
// ---------------------------------------------------------------------------
__device__ __forceinline__ uint32_t smem_u32(const void* p) {
    uint32_t a;
    asm("{ .reg .u64 t; cvta.to.shared.u64 t, %1; cvt.u32.u64 %0, t; }" : "=r"(a) : "l"(p));
    return a;
}
__device__ __forceinline__ float tf32r(float x) {
    uint32_t u;
    asm("cvt.rna.tf32.f32 %0, %1;" : "=r"(u) : "f"(x));
    return __uint_as_float(u);
}
__device__ __forceinline__ void cp16(uint32_t dst, const void* src) {
    asm volatile("cp.async.cg.shared.global [%0], [%1], 16;" :: "r"(dst), "l"(src) : "memory");
}
__device__ __forceinline__ void cp_commit() {
    asm volatile("cp.async.commit_group;" ::: "memory");
}
template <int N>
__device__ __forceinline__ void cp_wait() {
    asm volatile("cp.async.wait_group %0;" :: "n"(N) : "memory");
}

// m16n8k8 tf32 MMA: D = A*B + D
__device__ __forceinline__ void mma_tf32(float c[4], const uint32_t a[4], const uint32_t b[2]) {
    asm volatile(
        "mma.sync.aligned.m16n8k8.row.col.f32.tf32.tf32.f32 "
        "{%0,%1,%2,%3}, {%4,%5,%6,%7}, {%8,%9}, {%0,%1,%2,%3};"
        : "+f"(c[0]), "+f"(c[1]), "+f"(c[2]), "+f"(c[3])
        : "r"(a[0]), "r"(a[1]), "r"(a[2]), "r"(a[3]), "r"(b[0]), "r"(b[1]));
}

__device__ __forceinline__ float sigm(float x) { return 1.f / (1.f + __expf(-x)); }

// ---------------------------------------------------------------------------
// Tensor-core GEMM (TN): C[m,n] = sum_k A[m*K+k] * Bw[n*K+k] (+bias)
// Block 128x128, 256 threads = 8 warps (2 along M x 4 along N), warp tile
// 64x32, BK=32, 3-stage cp.async, 2 CTAs/SM (16 warps/SM = 4 per SMSP).
// Fused-LSTM mode (z != nullptr): epilogue applies LSTM cell, writes h & c.
// Requires gate-interleaved B/z layout (col n' = 4d + gate).
// h_out MUST NOT alias the A operand (ping-pong buffers in the launcher).
// ---------------------------------------------------------------------------
#define BK   32
#define ROWF 36                       // 32 + 4 pad floats per smem row
#define GTS  136                      // epilogue gate-tile row stride (floats)
#define STAGE_F ((128 + 128) * ROWF)  // 9216 floats per stage
#define GEMM_SMEM (3 * STAGE_F * 4)   // 110592 bytes

__global__ __launch_bounds__(256, 2)
void gemm_mma(const float* __restrict__ A, const float* __restrict__ Bw,
              float* __restrict__ C, int Nt, int K,
              const float* __restrict__ bias, int round_out,
              const float* __restrict__ z, const float* __restrict__ bsum,
              const float* __restrict__ c_in, float* __restrict__ c_out,
              float* __restrict__ h_out, int step, int round_h, int write_c)
{
    extern __shared__ float sm[];
    const int tid  = threadIdx.x;
    const int lane = tid & 31;
    const int wid  = tid >> 5;
    const int g    = lane >> 2;
    const int ctg  = lane & 3;
    const int wm   = (wid & 1) * 64;      // 2 warps along M
    const int wn   = (wid >> 1) * 32;     // 4 warps along N
    const int bm   = blockIdx.y * 128;
    const int bn   = blockIdx.x * 128;
    const int KT   = K / BK;
    const uint32_t sb = smem_u32(sm);

    auto load_stage = [&](int kt, int s) {
        const int k0 = kt * BK;
        const uint32_t ab = sb + (uint32_t)s * STAGE_F * 4;
        const uint32_t bb = ab + 128 * ROWF * 4;
        #pragma unroll
        for (int i = 0; i < 4; i++) {            // A: 128 rows x 8 float4
            int idx = tid + i * 256;
            int r = idx >> 3, c = idx & 7;
            cp16(ab + (uint32_t)(r * ROWF + c * 4) * 4,
                 A + (size_t)(bm + r) * K + k0 + c * 4);
        }
        #pragma unroll
        for (int i = 0; i < 4; i++) {            // B: 128 rows x 8 float4
            int idx = tid + i * 256;
            int r = idx >> 3, c = idx & 7;
            cp16(bb + (uint32_t)(r * ROWF + c * 4) * 4,
                 Bw + (size_t)(bn + r) * K + k0 + c * 4);
        }
    };

    float acc[4][4][4];
    #pragma unroll
    for (int mi = 0; mi < 4; mi++)
        #pragma unroll
        for (int ni = 0; ni < 4; ni++)
            #pragma unroll
            for (int t = 0; t < 4; t++) acc[mi][ni][t] = 0.f;

    // prologue: 2 stages in flight
    load_stage(0, 0); cp_commit();
    load_stage(1, 1); cp_commit();

    for (int kt = 0; kt < KT; kt++) {
        if (kt + 2 < KT) load_stage(kt + 2, (kt + 2) % 3);
        cp_commit();                    // uniform group count
        cp_wait<2>();                   // stage kt complete
        __syncthreads();

        const float* As = sm + (kt % 3) * STAGE_F;
        const float* Bs = As + 128 * ROWF;

        #pragma unroll
        for (int ks = 0; ks < 4; ks++) {
            uint32_t af[4][4], bf[4][2];
            #pragma unroll
            for (int mi = 0; mi < 4; mi++) {
                const float* p = As + (wm + mi * 16 + g) * ROWF + ks * 8 + ctg;
                af[mi][0] = *(const uint32_t*)(p);
                af[mi][1] = *(const uint32_t*)(p + 8 * ROWF);
                af[mi][2] = *(const uint32_t*)(p + 4);
                af[mi][3] = *(const uint32_t*)(p + 8 * ROWF + 4);
            }
            #pragma unroll
            for (int ni = 0; ni < 4; ni++) {
                const float* q = Bs + (wn + ni * 8 + g) * ROWF + ks * 8 + ctg;
                bf[ni][0] = *(const uint32_t*)(q);
                bf[ni][1] = *(const uint32_t*)(q + 4);
            }
            #pragma unroll
            for (int mi = 0; mi < 4; mi++)
                #pragma unroll
                for (int ni = 0; ni < 4; ni++)
                    mma_tf32(acc[mi][ni], af[mi], bf[ni]);
        }
        __syncthreads();
    }

    if (!z) {
        // ---- plain epilogue: bias + optional tf32 rounding ----
        #pragma unroll
        for (int ni = 0; ni < 4; ni++) {
            const int col = bn + wn + ni * 8 + 2 * ctg;
            float b0 = 0.f, b1 = 0.f;
            if (bias) { b0 = bias[col]; b1 = bias[col + 1]; }
            #pragma unroll
            for (int mi = 0; mi < 4; mi++) {
                const int row = bm + wm + mi * 16 + g;
                float v0 = acc[mi][ni][0] + b0;
                float v1 = acc[mi][ni][1] + b1;
                float v2 = acc[mi][ni][2] + b0;
                float v3 = acc[mi][ni][3] + b1;
                if (round_out) { v0 = tf32r(v0); v1 = tf32r(v1); v2 = tf32r(v2); v3 = tf32r(v3); }
                *(float2*)(C + (size_t)row * Nt + col)       = make_float2(v0, v1);
                *(float2*)(C + (size_t)(row + 8) * Nt + col) = make_float2(v2, v3);
            }
        }
    } else {
        // ---- fused LSTM epilogue ----
        // 1. accumulators -> smem gate tile [128][128] (row stride GTS)
        #pragma unroll
        for (int ni = 0; ni < 4; ni++) {
            const int cl = wn + ni * 8 + 2 * ctg;
            #pragma unroll
            for (int mi = 0; mi < 4; mi++) {
                const int rl = wm + mi * 16 + g;
                *(float2*)(sm + (size_t)rl * GTS + cl)       = make_float2(acc[mi][ni][0], acc[mi][ni][1]);
                *(float2*)(sm + (size_t)(rl + 8) * GTS + cl) = make_float2(acc[mi][ni][2], acc[mi][ni][3]);
            }
        }
        __syncthreads();

        // 2. pointwise LSTM cell over (row, d) items: 128 x 32 = 4096 items
        const int dn0 = bn >> 2;                     // 32 hidden units per N tile
        #pragma unroll
        for (int it = 0; it < 16; it++) {
            int idx = it * 256 + tid;
            int rl = idx >> 5, dl = idx & 31;
            int s = bm + rl, d = dn0 + dl;
            int l = s & 511, t = l - 8 + step;

            float4 gz;
            if (t >= 0) gz = *(const float4*)(z + (size_t)(s - 8 + step) * G4 + 4 * d);
            else        gz = *(const float4*)(bsum + 4 * d);

            float4 gr = *(const float4*)(sm + (size_t)rl * GTS + 4 * dl);
            float gi = gz.x + gr.x;
            float gf = gz.y + gr.y;
            float gg = gz.z + gr.z;
            float go = gz.w + gr.w;

            float c_prev = c_in[(size_t)s * D_MODEL + d];
            float cn = sigm(gf) * c_prev + sigm(gi) * tanhf(gg);
            float hn = sigm(go) * tanhf(cn);
            if (write_c) c_out[(size_t)s * D_MODEL + d] = cn;
            h_out[(size_t)s * D_MODEL + d] = round_h ? tf32r(hn) : hn;
        }
    }
}

// ---------------------------------------------------------------------------
// Weight permute + tf32 round: dst[(4d+g), k] = rna(src[(g*512+d), k])
// ---------------------------------------------------------------------------
__global__ void permute_round_w(const float* __restrict__ src, float* __restrict__ dst)
{
    int i = blockIdx.x * blockDim.x + threadIdx.x;      // float4 index
    if (i >= G4 * D_MODEL / 4) return;
    int np = i >> 7;                // dst row (0..2047)
    int c4 = (i & 127) * 4;
    int d = np >> 2, gg = np & 3;
    float4 v = *(const float4*)(src + (size_t)(gg * D_MODEL + d) * D_MODEL + c4);
    v.x = tf32r(v.x); v.y = tf32r(v.y); v.z = tf32r(v.z); v.w = tf32r(v.w);
    *(float4*)(dst + (size_t)np * D_MODEL + c4) = v;
}

__global__ void round_kernel(const float* __restrict__ src, float* __restrict__ dst, int n4)
{
    int i = blockIdx.x * blockDim.x + threadIdx.x;
    if (i >= n4) return;
    float4 v = ((const float4*)src)[i];
    v.x = tf32r(v.x); v.y = tf32r(v.y); v.z = tf32r(v.z); v.w = tf32r(v.w);
    ((float4*)dst)[i] = v;
}

__global__ void bsum_kernel(const float* __restrict__ bih, const float* __restrict__ bhh,
                            float* __restrict__ bs)
{
    int np = blockIdx.x * blockDim.x + threadIdx.x;
    if (np >= G4) return;
    int d = np >> 2, gg = np & 3;
    bs[np] = bih[gg * D_MODEL + d] + bhh[gg * D_MODEL + d];
}

// ---------------------------------------------------------------------------
// GLU: out[s,c] = a * sigmoid(b); rounded to tf32 (feeds conv GEMM)
// ---------------------------------------------------------------------------
__global__ void glu_kernel(const float* __restrict__ x, float* __restrict__ out)
{
    int idx = blockIdx.x * blockDim.x + threadIdx.x;
    if (idx >= S_ROWS * D_HALF / 4) return;
    int row = idx / (D_HALF / 4);
    int c4  = (idx % (D_HALF / 4)) * 4;
    const float* xr = x + (size_t)row * D_MODEL;
    float4 a = *(const float4*)(xr + c4);
    float4 b = *(const float4*)(xr + D_HALF + c4);
    float4 o;
    o.x = tf32r(a.x * sigm(b.x));
    o.y = tf32r(a.y * sigm(b.y));
    o.z = tf32r(a.z * sigm(b.z));
    o.w = tf32r(a.w * sigm(b.w));
    *(float4*)(out + (size_t)row * D_HALF + c4) = o;
}

// ---------------------------------------------------------------------------
// LSTM step 0 (h = c = 0): pointwise from gate-interleaved z only.
// ---------------------------------------------------------------------------
__global__ void lstm_step0(const float* __restrict__ z, const float* __restrict__ bsum,
                           float* __restrict__ c_out, float* __restrict__ h_out)
{
    int idx = blockIdx.x * blockDim.x + threadIdx.x;    // s*512 + d
    if (idx >= S_ROWS * D_MODEL) return;
    int s = idx >> 9, d = idx & 511, l = s & 511;
    float4 gz = (l >= 8) ? *(const float4*)(z + (size_t)(s - 8) * G4 + 4 * d)
                         : *(const float4*)(bsum + 4 * d);
    float cn = sigm(gz.x) * tanhf(gz.z);
    float hn = sigm(gz.w) * tanhf(cn);
    c_out[idx] = cn;
    h_out[idx] = tf32r(hn);
}

// ---------------------------------------------------------------------------
// Launcher
// ---------------------------------------------------------------------------
extern "C" void kernel_launch(void* const* d_in, const int* in_sizes, int n_in,
                              void* d_out, int out_size)
{
    const float* x      = (const float*)d_in[0];
    const float* conv_w = (const float*)d_in[1];
    const float* conv_b = (const float*)d_in[2];
    const float* w_ih   = (const float*)d_in[3];
    const float* w_hh   = (const float*)d_in[4];
    const float* b_ih   = (const float*)d_in[5];
    const float* b_hh   = (const float*)d_in[6];
    float* out = (float*)d_out;

    float *glu, *y, *z, *h0, *h1, *c, *wihp, *whhp, *convwr, *bsum;
    cudaGetSymbolAddress((void**)&glu,    g_glu);
    cudaGetSymbolAddress((void**)&y,      g_y);
    cudaGetSymbolAddress((void**)&z,      g_z);
    cudaGetSymbolAddress((void**)&h0,     g_h0);
    cudaGetSymbolAddress((void**)&h1,     g_h1);
    cudaGetSymbolAddress((void**)&c,      g_c);
    cudaGetSymbolAddress((void**)&wihp,   g_wih_p);
    cudaGetSymbolAddress((void**)&whhp,   g_whh_p);
    cudaGetSymbolAddress((void**)&convwr, g_convw_r);
    cudaGetSymbolAddress((void**)&bsum,   g_bsum);

    static int smem_set = 0;
    if (!smem_set) {
        cudaFuncSetAttribute(gemm_mma, cudaFuncAttributeMaxDynamicSharedMemorySize, GEMM_SMEM);
        smem_set = 1;
    }

    // 0. weight prep: permute + round recurrent weights, round conv, combine biases
    permute_round_w<<<(G4 * D_MODEL / 4 + 255) / 256, 256>>>(w_ih, wihp);
    permute_round_w<<<(G4 * D_MODEL / 4 + 255) / 256, 256>>>(w_hh, whhp);
    round_kernel<<<(D_MODEL * D_HALF / 4 + 255) / 256, 256>>>(conv_w, convwr, D_MODEL * D_HALF / 4);
    bsum_kernel<<<(G4 + 255) / 256, 256>>>(b_ih, b_hh, bsum);

    // 1. GLU (tf32-rounded output)
    glu_kernel<<<(S_ROWS * D_HALF / 4 + 255) / 256, 256>>>(x, glu);

    // 2. conv projection: y = glu @ conv_w^T + conv_b (8192x512, K=256), round y
    gemm_mma<<<dim3(D_MODEL / 128, S_ROWS / 128), 256, GEMM_SMEM>>>(
        glu, convwr, y, D_MODEL, D_HALF, conv_b, 1,
        nullptr, nullptr, nullptr, nullptr, nullptr, 0, 0, 0);

    // 3. z = y @ w_ih_p^T + bsum   (8192x2048, K=512, gate-interleaved cols)
    gemm_mma<<<dim3(G4 / 128, S_ROWS / 128), 256, GEMM_SMEM>>>(
        y, wihp, z, G4, D_MODEL, bsum, 0,
        nullptr, nullptr, nullptr, nullptr, nullptr, 0, 0, 0);

    // 4. step 0 pointwise (h = c = 0) -> h0
    lstm_step0<<<(S_ROWS * D_MODEL + 255) / 256, 256>>>(z, bsum, c, h0);

    // 5. steps 1..8: fused recurrent GEMM + LSTM cell, ping-pong h buffers
    float* hb[2] = {h0, h1};
    for (int k = 1; k <= 8; k++) {
        const float* h_in = hb[(k - 1) & 1];
        float* h_out = (k == 8) ? out : hb[k & 1];
        gemm_mma<<<dim3(G4 / 128, S_ROWS / 128), 256, GEMM_SMEM>>>(
            h_in, whhp, nullptr, G4, D_MODEL, nullptr, 0,
            z, bsum, c, c, h_out, k, (k < 8) ? 1 : 0, (k < 8) ? 1 : 0);
    }
}

// round 8
// speedup vs baseline: 4.4087x; 1.4953x over previous
#include <cuda_runtime.h>
#include <cuda_fp16.h>
#include <cstdint>
#include <cstddef>

// Problem dims (fixed)
#define S_ROWS  8192      // B*L = 16*512
#define D_MODEL 512
#define D_HALF  256
#define G4      2048      // 4*D_MODEL

// ---------------------------------------------------------------------------
// Scratch (static device arrays — no runtime allocation)
// ---------------------------------------------------------------------------
__device__ __half g_glu[S_ROWS * D_HALF];
__device__ __half g_y[S_ROWS * D_MODEL];
__device__ float  g_z[(size_t)S_ROWS * G4];     // gate-interleaved cols: n' = 4d+g
__device__ __half g_h0[S_ROWS * D_MODEL];       // ping-pong h buffers (no WAR race)
__device__ __half g_h1[S_ROWS * D_MODEL];
__device__ float  g_c[S_ROWS * D_MODEL];
__device__ __half g_wih_p[G4 * D_MODEL];        // permuted + fp16 weights
__device__ __half g_whh_p[G4 * D_MODEL];
__device__ __half g_convw_r[D_MODEL * D_HALF];
__device__ float  g_bsum[G4];                   // b_ih + b_hh, permuted (fp32)

// ---------------------------------------------------------------------------
// Helpers (base PTX only)
// ---------------------------------------------------------------------------
__device__ __forceinline__ uint32_t smem_u32(const void* p) {
    uint32_t a;
    asm("{ .reg .u64 t; cvta.to.shared.u64 t, %1; cvt.u32.u64 %0, t; }" : "=r"(a) : "l"(p));
    return a;
}
__device__ __forceinline__ void cp16(uint32_t dst, const void* src) {
    asm volatile("cp.async.cg.shared.global [%0], [%1], 16;" :: "r"(dst), "l"(src) : "memory");
}
__device__ __forceinline__ void cp_commit() {
    asm volatile("cp.async.commit_group;" ::: "memory");
}
template <int N>
__device__ __forceinline__ void cp_wait() {
    asm volatile("cp.async.wait_group %0;" :: "n"(N) : "memory");
}

// m16n8k16 fp16 MMA, fp32 accumulate: D = A*B + D
__device__ __forceinline__ void mma_f16(float c[4], const uint32_t a[4], const uint32_t b[2]) {
    asm volatile(
        "mma.sync.aligned.m16n8k16.row.col.f32.f16.f16.f32 "
        "{%0,%1,%2,%3}, {%4,%5,%6,%7}, {%8,%9}, {%0,%1,%2,%3};"
        : "+f"(c[0]), "+f"(c[1]), "+f"(c[2]), "+f"(c[3])
        : "r"(a[0]), "r"(a[1]), "r"(a[2]), "r"(a[3]), "r"(b[0]), "r"(b[1]));
}

__device__ __forceinline__ float sigm(float x) { return 1.f / (1.f + __expf(-x)); }

// ---------------------------------------------------------------------------
// fp16 tensor-core GEMM (TN): C[m,n] = sum_k A[m*K+k] * Bw[n*K+k] (+bias)
// Block 128x128, 8 warps (2 M x 4 N), warp tile 64x32, BK=64 halves,
// 3-stage cp.async, 2 CTAs/SM. fp32 accumulate.
// Fused-LSTM mode (z != nullptr): epilogue applies LSTM cell, writes h & c.
// Gate-interleaved B/z layout (col n' = 4d + gate). h_out must not alias A.
// ---------------------------------------------------------------------------
#define BK      64                     // halves per K panel
#define ROW32   36                     // uint32 per smem row (32 data + 4 pad)
#define STAGE32 ((128 + 128) * ROW32)  // 9216 uint32 per stage
#define GEMM_SMEM (3 * STAGE32 * 4)    // 110592 bytes
#define GTS     136                    // epilogue gate-tile row stride (floats)

__global__ __launch_bounds__(256, 2)
void gemm_mma(const __half* __restrict__ A, const __half* __restrict__ Bw,
              void* __restrict__ C, int Nt, int K,
              const float* __restrict__ bias, int out_half,
              const float* __restrict__ z, const float* __restrict__ bsum,
              const float* __restrict__ c_in, float* __restrict__ c_out,
              __half* __restrict__ h_out_h, float* __restrict__ h_out_f,
              int step, int write_c)
{
    extern __shared__ uint32_t sm32[];
    const int tid  = threadIdx.x;
    const int lane = tid & 31;
    const int wid  = tid >> 5;
    const int g    = lane >> 2;
    const int ctg  = lane & 3;
    const int wm   = (wid & 1) * 64;      // 2 warps along M
    const int wn   = (wid >> 1) * 32;     // 4 warps along N
    const int bm   = blockIdx.y * 128;
    const int bn   = blockIdx.x * 128;
    const int KT   = K / BK;
    const uint32_t sb = smem_u32(sm32);

    auto load_stage = [&](int kt, int s) {
        const int k0 = kt * BK;
        const uint32_t ab = sb + (uint32_t)s * STAGE32 * 4;
        const uint32_t bb = ab + 128 * ROW32 * 4;
        #pragma unroll
        for (int i = 0; i < 4; i++) {            // A: 128 rows x 8 granules(16B)
            int idx = tid + i * 256;
            int r = idx >> 3, c = idx & 7;
            cp16(ab + (uint32_t)(r * ROW32 + c * 4) * 4,
                 A + (size_t)(bm + r) * K + k0 + c * 8);
        }
        #pragma unroll
        for (int i = 0; i < 4; i++) {            // B: 128 rows x 8 granules
            int idx = tid + i * 256;
            int r = idx >> 3, c = idx & 7;
            cp16(bb + (uint32_t)(r * ROW32 + c * 4) * 4,
                 Bw + (size_t)(bn + r) * K + k0 + c * 8);
        }
    };

    float acc[4][4][4];
    #pragma unroll
    for (int mi = 0; mi < 4; mi++)
        #pragma unroll
        for (int ni = 0; ni < 4; ni++)
            #pragma unroll
            for (int t = 0; t < 4; t++) acc[mi][ni][t] = 0.f;

    load_stage(0, 0); cp_commit();
    load_stage(1, 1); cp_commit();

    for (int kt = 0; kt < KT; kt++) {
        if (kt + 2 < KT) load_stage(kt + 2, (kt + 2) % 3);
        cp_commit();                    // uniform group count
        cp_wait<2>();                   // stage kt complete
        __syncthreads();

        const uint32_t* As = sm32 + (kt % 3) * STAGE32;
        const uint32_t* Bs = As + 128 * ROW32;

        #pragma unroll
        for (int ks = 0; ks < 4; ks++) {          // 4 x k16 per panel
            uint32_t af[4][4], bf[4][2];
            #pragma unroll
            for (int mi = 0; mi < 4; mi++) {
                const uint32_t* p = As + (wm + mi * 16 + g) * ROW32 + ks * 8 + ctg;
                af[mi][0] = p[0];
                af[mi][1] = p[8 * ROW32];
                af[mi][2] = p[4];
                af[mi][3] = p[8 * ROW32 + 4];
            }
            #pragma unroll
            for (int ni = 0; ni < 4; ni++) {
                const uint32_t* q = Bs + (wn + ni * 8 + g) * ROW32 + ks * 8 + ctg;
                bf[ni][0] = q[0];
                bf[ni][1] = q[4];
            }
            #pragma unroll
            for (int mi = 0; mi < 4; mi++)
                #pragma unroll
                for (int ni = 0; ni < 4; ni++)
                    mma_f16(acc[mi][ni], af[mi], bf[ni]);
        }
        __syncthreads();
    }

    if (!z) {
        // ---- plain epilogue: bias, write fp16 or fp32 ----
        #pragma unroll
        for (int ni = 0; ni < 4; ni++) {
            const int col = bn + wn + ni * 8 + 2 * ctg;
            float b0 = 0.f, b1 = 0.f;
            if (bias) { b0 = bias[col]; b1 = bias[col + 1]; }
            #pragma unroll
            for (int mi = 0; mi < 4; mi++) {
                const int row = bm + wm + mi * 16 + g;
                float v0 = acc[mi][ni][0] + b0;
                float v1 = acc[mi][ni][1] + b1;
                float v2 = acc[mi][ni][2] + b0;
                float v3 = acc[mi][ni][3] + b1;
                if (out_half) {
                    __half* Ch = (__half*)C;
                    *(__half2*)(Ch + (size_t)row * Nt + col)       = __floats2half2_rn(v0, v1);
                    *(__half2*)(Ch + (size_t)(row + 8) * Nt + col) = __floats2half2_rn(v2, v3);
                } else {
                    float* Cf = (float*)C;
                    *(float2*)(Cf + (size_t)row * Nt + col)       = make_float2(v0, v1);
                    *(float2*)(Cf + (size_t)(row + 8) * Nt + col) = make_float2(v2, v3);
                }
            }
        }
    } else {
        // ---- fused LSTM epilogue ----
        float* smf = (float*)sm32;
        #pragma unroll
        for (int ni = 0; ni < 4; ni++) {
            const int cl = wn + ni * 8 + 2 * ctg;
            #pragma unroll
            for (int mi = 0; mi < 4; mi++) {
                const int rl = wm + mi * 16 + g;
                *(float2*)(smf + (size_t)rl * GTS + cl)       = make_float2(acc[mi][ni][0], acc[mi][ni][1]);
                *(float2*)(smf + (size_t)(rl + 8) * GTS + cl) = make_float2(acc[mi][ni][2], acc[mi][ni][3]);
            }
        }
        __syncthreads();

        const int dn0 = bn >> 2;                     // 32 hidden units per N tile
        #pragma unroll
        for (int it = 0; it < 16; it++) {
            int idx = it * 256 + tid;
            int rl = idx >> 5, dl = idx & 31;
            int s = bm + rl, d = dn0 + dl;
            int l = s & 511, t = l - 8 + step;

            float4 gz;
            if (t >= 0) gz = *(const float4*)(z + (size_t)(s - 8 + step) * G4 + 4 * d);
            else        gz = *(const float4*)(bsum + 4 * d);

            float4 gr = *(const float4*)(smf + (size_t)rl * GTS + 4 * dl);
            float gi = gz.x + gr.x;
            float gf = gz.y + gr.y;
            float gg = gz.z + gr.z;
            float go = gz.w + gr.w;

            float c_prev = c_in[(size_t)s * D_MODEL + d];
            float cn = sigm(gf) * c_prev + sigm(gi) * tanhf(gg);
            float hn = sigm(go) * tanhf(cn);
            if (write_c) c_out[(size_t)s * D_MODEL + d] = cn;
            if (h_out_h) h_out_h[(size_t)s * D_MODEL + d] = __float2half_rn(hn);
            else         h_out_f[(size_t)s * D_MODEL + d] = hn;
        }
    }
}

// ---------------------------------------------------------------------------
// Weight permute to fp16: dst[(4d+g), k] = fp16(src[(g*512+d), k])
// ---------------------------------------------------------------------------
__global__ void permute_w_h(const float* __restrict__ src, __half* __restrict__ dst)
{
    int i = blockIdx.x * blockDim.x + threadIdx.x;      // float4 index
    if (i >= G4 * D_MODEL / 4) return;
    int np = i >> 7;                // dst row (0..2047)
    int c4 = (i & 127) * 4;
    int d = np >> 2, gg = np & 3;
    float4 v = *(const float4*)(src + (size_t)(gg * D_MODEL + d) * D_MODEL + c4);
    __half* o = dst + (size_t)np * D_MODEL + c4;
    *(__half2*)(o)     = __floats2half2_rn(v.x, v.y);
    *(__half2*)(o + 2) = __floats2half2_rn(v.z, v.w);
}

__global__ void round_h_kernel(const float* __restrict__ src, __half* __restrict__ dst, int n4)
{
    int i = blockIdx.x * blockDim.x + threadIdx.x;
    if (i >= n4) return;
    float4 v = ((const float4*)src)[i];
    __half* o = dst + (size_t)i * 4;
    *(__half2*)(o)     = __floats2half2_rn(v.x, v.y);
    *(__half2*)(o + 2) = __floats2half2_rn(v.z, v.w);
}

__global__ void bsum_kernel(const float* __restrict__ bih, const float* __restrict__ bhh,
                            float* __restrict__ bs)
{
    int np = blockIdx.x * blockDim.x + threadIdx.x;
    if (np >= G4) return;
    int d = np >> 2, gg = np & 3;
    bs[np] = bih[gg * D_MODEL + d] + bhh[gg * D_MODEL + d];
}

// ---------------------------------------------------------------------------
// GLU: out[s,c] = fp16(a * sigmoid(b))
// ---------------------------------------------------------------------------
__global__ void glu_kernel(const float* __restrict__ x, __half* __restrict__ out)
{
    int idx = blockIdx.x * blockDim.x + threadIdx.x;
    if (idx >= S_ROWS * D_HALF / 4) return;
    int row = idx / (D_HALF / 4);
    int c4  = (idx % (D_HALF / 4)) * 4;
    const float* xr = x + (size_t)row * D_MODEL;
    float4 a = *(const float4*)(xr + c4);
    float4 b = *(const float4*)(xr + D_HALF + c4);
    __half* o = out + (size_t)row * D_HALF + c4;
    *(__half2*)(o)     = __floats2half2_rn(a.x * sigm(b.x), a.y * sigm(b.y));
    *(__half2*)(o + 2) = __floats2half2_rn(a.z * sigm(b.z), a.w * sigm(b.w));
}

// ---------------------------------------------------------------------------
// LSTM step 0 (h = c = 0): pointwise from gate-interleaved z only.
// ---------------------------------------------------------------------------
__global__ void lstm_step0(const float* __restrict__ z, const float* __restrict__ bsum,
                           float* __restrict__ c_out, __half* __restrict__ h_out)
{
    int idx = blockIdx.x * blockDim.x + threadIdx.x;    // s*512 + d
    if (idx >= S_ROWS * D_MODEL) return;
    int s = idx >> 9, d = idx & 511, l = s & 511;
    float4 gz = (l >= 8) ? *(const float4*)(z + (size_t)(s - 8) * G4 + 4 * d)
                         : *(const float4*)(bsum + 4 * d);
    float cn = sigm(gz.x) * tanhf(gz.z);
    float hn = sigm(gz.w) * tanhf(cn);
    c_out[idx] = cn;
    h_out[idx] = __float2half_rn(hn);
}

// ---------------------------------------------------------------------------
// Launcher
// ---------------------------------------------------------------------------
extern "C" void kernel_launch(void* const* d_in, const int* in_sizes, int n_in,
                              void* d_out, int out_size)
{
    const float* x      = (const float*)d_in[0];
    const float* conv_w = (const float*)d_in[1];
    const float* conv_b = (const float*)d_in[2];
    const float* w_ih   = (const float*)d_in[3];
    const float* w_hh   = (const float*)d_in[4];
    const float* b_ih   = (const float*)d_in[5];
    const float* b_hh   = (const float*)d_in[6];
    float* out = (float*)d_out;

    __half *glu, *y, *h0, *h1, *wihp, *whhp, *convwr;
    float *z, *c, *bsum;
    cudaGetSymbolAddress((void**)&glu,    g_glu);
    cudaGetSymbolAddress((void**)&y,      g_y);
    cudaGetSymbolAddress((void**)&z,      g_z);
    cudaGetSymbolAddress((void**)&h0,     g_h0);
    cudaGetSymbolAddress((void**)&h1,     g_h1);
    cudaGetSymbolAddress((void**)&c,      g_c);
    cudaGetSymbolAddress((void**)&wihp,   g_wih_p);
    cudaGetSymbolAddress((void**)&whhp,   g_whh_p);
    cudaGetSymbolAddress((void**)&convwr, g_convw_r);
    cudaGetSymbolAddress((void**)&bsum,   g_bsum);

    static int smem_set = 0;
    if (!smem_set) {
        cudaFuncSetAttribute(gemm_mma, cudaFuncAttributeMaxDynamicSharedMemorySize, GEMM_SMEM);
        smem_set = 1;
    }

    // 0. weight prep
    permute_w_h<<<(G4 * D_MODEL / 4 + 255) / 256, 256>>>(w_ih, wihp);
    permute_w_h<<<(G4 * D_MODEL / 4 + 255) / 256, 256>>>(w_hh, whhp);
    round_h_kernel<<<(D_MODEL * D_HALF / 4 + 255) / 256, 256>>>(conv_w, convwr, D_MODEL * D_HALF / 4);
    bsum_kernel<<<(G4 + 255) / 256, 256>>>(b_ih, b_hh, bsum);

    // 1. GLU -> fp16
    glu_kernel<<<(S_ROWS * D_HALF / 4 + 255) / 256, 256>>>(x, glu);

    // 2. conv projection: y = glu @ conv_w^T + conv_b (8192x512, K=256) -> fp16
    gemm_mma<<<dim3(D_MODEL / 128, S_ROWS / 128), 256, GEMM_SMEM>>>(
        glu, convwr, y, D_MODEL, D_HALF, conv_b, 1,
        nullptr, nullptr, nullptr, nullptr, nullptr, nullptr, 0, 0);

    // 3. z = y @ w_ih_p^T + bsum (8192x2048, K=512, gate-interleaved) -> fp32
    gemm_mma<<<dim3(G4 / 128, S_ROWS / 128), 256, GEMM_SMEM>>>(
        y, wihp, z, G4, D_MODEL, bsum, 0,
        nullptr, nullptr, nullptr, nullptr, nullptr, nullptr, 0, 0);

    // 4. step 0 pointwise (h = c = 0) -> h0
    lstm_step0<<<(S_ROWS * D_MODEL + 255) / 256, 256>>>(z, bsum, c, h0);

    // 5. steps 1..8: fused recurrent GEMM + LSTM cell, ping-pong h buffers
    __half* hb[2] = {h0, h1};
    for (int k = 1; k <= 8; k++) {
        const __half* h_in = hb[(k - 1) & 1];
        __half* hh = (k == 8) ? nullptr : hb[k & 1];
        float*  hf = (k == 8) ? out : nullptr;
        gemm_mma<<<dim3(G4 / 128, S_ROWS / 128), 256, GEMM_SMEM>>>(
            h_in, whhp, nullptr, G4, D_MODEL, nullptr, 0,
            z, bsum, c, c, hh, hf, k, (k < 8) ? 1 : 0);
    }
}

// round 9
// speedup vs baseline: 5.0332x; 1.1417x over previous
#include <cuda_runtime.h>
#include <cuda_fp16.h>
#include <cstdint>
#include <cstddef>

// Problem dims (fixed)
#define S_ROWS  8192      // B*L = 16*512
#define D_MODEL 512
#define D_HALF  256
#define G4      2048      // 4*D_MODEL

#define ZSCALE  2048.0f
#define ZINV    (1.0f / 2048.0f)

// ---------------------------------------------------------------------------
// Scratch (static device arrays — no runtime allocation)
// ---------------------------------------------------------------------------
__device__ __half g_glu[S_ROWS * D_HALF];
__device__ __half g_y[S_ROWS * D_MODEL];
__device__ short  g_z[(size_t)S_ROWS * G4];     // gate-interleaved, int16 x2048
__device__ __half g_h0[S_ROWS * D_MODEL];       // ping-pong h buffers (no WAR race)
__device__ __half g_h1[S_ROWS * D_MODEL];
__device__ float  g_c[S_ROWS * D_MODEL];
__device__ __half g_wih_p[G4 * D_MODEL];        // permuted fp16 weights
__device__ __half g_whh_p[G4 * D_MODEL];
__device__ __half g_convw_r[D_MODEL * D_HALF];
__device__ float  g_bsum[G4];                   // b_ih + b_hh, permuted (fp32)

// ---------------------------------------------------------------------------
// Helpers (base PTX only)
// ---------------------------------------------------------------------------
__device__ __forceinline__ uint32_t smem_u32(const void* p) {
    uint32_t a;
    asm("{ .reg .u64 t; cvta.to.shared.u64 t, %1; cvt.u32.u64 %0, t; }" : "=r"(a) : "l"(p));
    return a;
}
__device__ __forceinline__ void cp16(uint32_t dst, const void* src) {
    asm volatile("cp.async.cg.shared.global [%0], [%1], 16;" :: "r"(dst), "l"(src) : "memory");
}
__device__ __forceinline__ void cp_commit() {
    asm volatile("cp.async.commit_group;" ::: "memory");
}
template <int N>
__device__ __forceinline__ void cp_wait() {
    asm volatile("cp.async.wait_group %0;" :: "n"(N) : "memory");
}

// m16n8k16 fp16 MMA, fp32 accumulate: D = A*B + D
__device__ __forceinline__ void mma_f16(float c[4], const uint32_t a[4], const uint32_t b[2]) {
    asm volatile(
        "mma.sync.aligned.m16n8k16.row.col.f32.f16.f16.f32 "
        "{%0,%1,%2,%3}, {%4,%5,%6,%7}, {%8,%9}, {%0,%1,%2,%3};"
        : "+f"(c[0]), "+f"(c[1]), "+f"(c[2]), "+f"(c[3])
        : "r"(a[0]), "r"(a[1]), "r"(a[2]), "r"(a[3]), "r"(b[0]), "r"(b[1]));
}

__device__ __forceinline__ float sigm(float x) { return 1.f / (1.f + __expf(-x)); }
__device__ __forceinline__ short zq(float v) {
    return (short)__float2int_rn(fminf(fmaxf(v, -15.9f), 15.9f) * ZSCALE);
}

// ---------------------------------------------------------------------------
// fp16 tensor-core GEMM (TN): C[m,n] = sum_k A[m*K+k] * Bw[n*K+k] (+bias)
// Block 128x128, 8 warps (2 M x 4 N), warp tile 64x32, BK=64 halves,
// 3-stage cp.async, 2 CTAs/SM. fp32 accumulate.
// out_mode: 1 = fp16 C, 2 = int16 z-quantized C.
// Fused-LSTM mode (z != nullptr): epilogue applies LSTM cell, writes h & c.
// Gate-interleaved B/z layout (col n' = 4d + gate). h_out must not alias A.
// ---------------------------------------------------------------------------
#define BK      64                     // halves per K panel
#define ROW32   36                     // uint32 per smem row (32 data + 4 pad)
#define STAGE32 ((128 + 128) * ROW32)  // 9216 uint32 per stage
#define GEMM_SMEM (3 * STAGE32 * 4)    // 110592 bytes
#define GTS     136                    // epilogue gate-tile row stride (floats)

__global__ __launch_bounds__(256, 2)
void gemm_mma(const __half* __restrict__ A, const __half* __restrict__ Bw,
              void* __restrict__ C, int Nt, int K,
              const float* __restrict__ bias, int out_mode,
              const short* __restrict__ z, const float* __restrict__ bsum,
              const float* __restrict__ c_in, float* __restrict__ c_out,
              __half* __restrict__ h_out_h, float* __restrict__ h_out_f,
              int step, int write_c)
{
    extern __shared__ uint32_t sm32[];
    const int tid  = threadIdx.x;
    const int lane = tid & 31;
    const int wid  = tid >> 5;
    const int g    = lane >> 2;
    const int ctg  = lane & 3;
    const int wm   = (wid & 1) * 64;      // 2 warps along M
    const int wn   = (wid >> 1) * 32;     // 4 warps along N
    const int bm   = blockIdx.y * 128;
    const int bn   = blockIdx.x * 128;
    const int KT   = K / BK;
    const uint32_t sb = smem_u32(sm32);

    auto load_stage = [&](int kt, int s) {
        const int k0 = kt * BK;
        const uint32_t ab = sb + (uint32_t)s * STAGE32 * 4;
        const uint32_t bb = ab + 128 * ROW32 * 4;
        #pragma unroll
        for (int i = 0; i < 4; i++) {            // A: 128 rows x 8 granules(16B)
            int idx = tid + i * 256;
            int r = idx >> 3, c = idx & 7;
            cp16(ab + (uint32_t)(r * ROW32 + c * 4) * 4,
                 A + (size_t)(bm + r) * K + k0 + c * 8);
        }
        #pragma unroll
        for (int i = 0; i < 4; i++) {            // B: 128 rows x 8 granules
            int idx = tid + i * 256;
            int r = idx >> 3, c = idx & 7;
            cp16(bb + (uint32_t)(r * ROW32 + c * 4) * 4,
                 Bw + (size_t)(bn + r) * K + k0 + c * 8);
        }
    };

    float acc[4][4][4];
    #pragma unroll
    for (int mi = 0; mi < 4; mi++)
        #pragma unroll
        for (int ni = 0; ni < 4; ni++)
            #pragma unroll
            for (int t = 0; t < 4; t++) acc[mi][ni][t] = 0.f;

    load_stage(0, 0); cp_commit();
    load_stage(1, 1); cp_commit();

    for (int kt = 0; kt < KT; kt++) {
        if (kt + 2 < KT) load_stage(kt + 2, (kt + 2) % 3);
        cp_commit();                    // uniform group count
        cp_wait<2>();                   // stage kt complete
        __syncthreads();

        const uint32_t* As = sm32 + (kt % 3) * STAGE32;
        const uint32_t* Bs = As + 128 * ROW32;

        #pragma unroll
        for (int ks = 0; ks < 4; ks++) {          // 4 x k16 per panel
            uint32_t af[4][4], bf[4][2];
            #pragma unroll
            for (int mi = 0; mi < 4; mi++) {
                const uint32_t* p = As + (wm + mi * 16 + g) * ROW32 + ks * 8 + ctg;
                af[mi][0] = p[0];
                af[mi][1] = p[8 * ROW32];
                af[mi][2] = p[4];
                af[mi][3] = p[8 * ROW32 + 4];
            }
            #pragma unroll
            for (int ni = 0; ni < 4; ni++) {
                const uint32_t* q = Bs + (wn + ni * 8 + g) * ROW32 + ks * 8 + ctg;
                bf[ni][0] = q[0];
                bf[ni][1] = q[4];
            }
            #pragma unroll
            for (int mi = 0; mi < 4; mi++)
                #pragma unroll
                for (int ni = 0; ni < 4; ni++)
                    mma_f16(acc[mi][ni], af[mi], bf[ni]);
        }
        __syncthreads();
    }

    if (!z) {
        // ---- plain epilogue: bias, write fp16 (mode 1) or int16 z (mode 2) ----
        #pragma unroll
        for (int ni = 0; ni < 4; ni++) {
            const int col = bn + wn + ni * 8 + 2 * ctg;
            float b0 = 0.f, b1 = 0.f;
            if (bias) { b0 = bias[col]; b1 = bias[col + 1]; }
            #pragma unroll
            for (int mi = 0; mi < 4; mi++) {
                const int row = bm + wm + mi * 16 + g;
                float v0 = acc[mi][ni][0] + b0;
                float v1 = acc[mi][ni][1] + b1;
                float v2 = acc[mi][ni][2] + b0;
                float v3 = acc[mi][ni][3] + b1;
                if (out_mode == 1) {
                    __half* Ch = (__half*)C;
                    *(__half2*)(Ch + (size_t)row * Nt + col)       = __floats2half2_rn(v0, v1);
                    *(__half2*)(Ch + (size_t)(row + 8) * Nt + col) = __floats2half2_rn(v2, v3);
                } else {
                    short* Cs = (short*)C;
                    *(short2*)(Cs + (size_t)row * Nt + col)       = make_short2(zq(v0), zq(v1));
                    *(short2*)(Cs + (size_t)(row + 8) * Nt + col) = make_short2(zq(v2), zq(v3));
                }
            }
        }
    } else {
        // ---- fused LSTM epilogue ----
        float* smf = (float*)sm32;
        #pragma unroll
        for (int ni = 0; ni < 4; ni++) {
            const int cl = wn + ni * 8 + 2 * ctg;
            #pragma unroll
            for (int mi = 0; mi < 4; mi++) {
                const int rl = wm + mi * 16 + g;
                *(float2*)(smf + (size_t)rl * GTS + cl)       = make_float2(acc[mi][ni][0], acc[mi][ni][1]);
                *(float2*)(smf + (size_t)(rl + 8) * GTS + cl) = make_float2(acc[mi][ni][2], acc[mi][ni][3]);
            }
        }
        __syncthreads();

        const int dn0 = bn >> 2;                     // 32 hidden units per N tile
        #pragma unroll
        for (int it = 0; it < 16; it++) {
            int idx = it * 256 + tid;
            int rl = idx >> 5, dl = idx & 31;
            int s = bm + rl, d = dn0 + dl;
            int l = s & 511, t = l - 8 + step;

            float4 gz;
            if (t >= 0) {
                short4 q = *(const short4*)(z + (size_t)(s - 8 + step) * G4 + 4 * d);
                gz = make_float4(q.x * ZINV, q.y * ZINV, q.z * ZINV, q.w * ZINV);
            } else {
                gz = *(const float4*)(bsum + 4 * d);
            }

            float4 gr = *(const float4*)(smf + (size_t)rl * GTS + 4 * dl);
            float gi = gz.x + gr.x;
            float gf = gz.y + gr.y;
            float gg = gz.z + gr.z;
            float go = gz.w + gr.w;

            float c_prev = c_in[(size_t)s * D_MODEL + d];
            float cn = sigm(gf) * c_prev + sigm(gi) * tanhf(gg);
            float hn = sigm(go) * tanhf(cn);
            if (write_c) c_out[(size_t)s * D_MODEL + d] = cn;
            if (h_out_h) h_out_h[(size_t)s * D_MODEL + d] = __float2half_rn(hn);
            else         h_out_f[(size_t)s * D_MODEL + d] = hn;
        }
    }
}

// ---------------------------------------------------------------------------
// Merged prep kernel: permute+convert both recurrent weights, round conv
// weights, combine biases. One grid-stride pass over segmented index space.
// ---------------------------------------------------------------------------
#define WSEG   (G4 * D_MODEL / 4)          // 262144 float4 per weight matrix
#define CSEG   (D_MODEL * D_HALF / 4)      // 32768
#define BSEG   (G4 / 4)                    // 512
#define PREP_TOTAL (2 * WSEG + CSEG + BSEG)

__global__ void prep_kernel(const float* __restrict__ w_ih, const float* __restrict__ w_hh,
                            const float* __restrict__ conv_w,
                            const float* __restrict__ b_ih, const float* __restrict__ b_hh,
                            __half* __restrict__ wihp, __half* __restrict__ whhp,
                            __half* __restrict__ convwr, float* __restrict__ bsum)
{
    int i = blockIdx.x * blockDim.x + threadIdx.x;
    if (i >= PREP_TOTAL) return;

    if (i < 2 * WSEG) {
        const float* src = (i < WSEG) ? w_ih : w_hh;
        __half* dst = (i < WSEG) ? wihp : whhp;
        int j = (i < WSEG) ? i : i - WSEG;
        int np = j >> 7;                 // dst row (0..2047)
        int c4 = (j & 127) * 4;
        int d = np >> 2, gg = np & 3;
        float4 v = *(const float4*)(src + (size_t)(gg * D_MODEL + d) * D_MODEL + c4);
        __half* o = dst + (size_t)np * D_MODEL + c4;
        *(__half2*)(o)     = __floats2half2_rn(v.x, v.y);
        *(__half2*)(o + 2) = __floats2half2_rn(v.z, v.w);
    } else if (i < 2 * WSEG + CSEG) {
        int j = i - 2 * WSEG;
        float4 v = ((const float4*)conv_w)[j];
        __half* o = convwr + (size_t)j * 4;
        *(__half2*)(o)     = __floats2half2_rn(v.x, v.y);
        *(__half2*)(o + 2) = __floats2half2_rn(v.z, v.w);
    } else {
        int j = i - 2 * WSEG - CSEG;     // 4 bsum entries
        #pragma unroll
        for (int t = 0; t < 4; t++) {
            int np = j * 4 + t;
            int d = np >> 2, gg = np & 3;
            bsum[np] = b_ih[gg * D_MODEL + d] + b_hh[gg * D_MODEL + d];
        }
    }
}

// ---------------------------------------------------------------------------
// GLU: out[s,c] = fp16(a * sigmoid(b))
// ---------------------------------------------------------------------------
__global__ void glu_kernel(const float* __restrict__ x, __half* __restrict__ out)
{
    int idx = blockIdx.x * blockDim.x + threadIdx.x;
    if (idx >= S_ROWS * D_HALF / 4) return;
    int row = idx / (D_HALF / 4);
    int c4  = (idx % (D_HALF / 4)) * 4;
    const float* xr = x + (size_t)row * D_MODEL;
    float4 a = *(const float4*)(xr + c4);
    float4 b = *(const float4*)(xr + D_HALF + c4);
    __half* o = out + (size_t)row * D_HALF + c4;
    *(__half2*)(o)     = __floats2half2_rn(a.x * sigm(b.x), a.y * sigm(b.y));
    *(__half2*)(o + 2) = __floats2half2_rn(a.z * sigm(b.z), a.w * sigm(b.w));
}

// ---------------------------------------------------------------------------
// LSTM step 0 (h = c = 0): pointwise from gate-interleaved int16 z.
// ---------------------------------------------------------------------------
__global__ void lstm_step0(const short* __restrict__ z, const float* __restrict__ bsum,
                           float* __restrict__ c_out, __half* __restrict__ h_out)
{
    int idx = blockIdx.x * blockDim.x + threadIdx.x;    // s*512 + d
    if (idx >= S_ROWS * D_MODEL) return;
    int s = idx >> 9, d = idx & 511, l = s & 511;
    float4 gz;
    if (l >= 8) {
        short4 q = *(const short4*)(z + (size_t)(s - 8) * G4 + 4 * d);
        gz = make_float4(q.x * ZINV, q.y * ZINV, q.z * ZINV, q.w * ZINV);
    } else {
        gz = *(const float4*)(bsum + 4 * d);
    }
    float cn = sigm(gz.x) * tanhf(gz.z);
    float hn = sigm(gz.w) * tanhf(cn);
    c_out[idx] = cn;
    h_out[idx] = __float2half_rn(hn);
}

// ---------------------------------------------------------------------------
// Launcher
// ---------------------------------------------------------------------------
extern "C" void kernel_launch(void* const* d_in, const int* in_sizes, int n_in,
                              void* d_out, int out_size)
{
    const float* x      = (const float*)d_in[0];
    const float* conv_w = (const float*)d_in[1];
    const float* conv_b = (const float*)d_in[2];
    const float* w_ih   = (const float*)d_in[3];
    const float* w_hh   = (const float*)d_in[4];
    const float* b_ih   = (const float*)d_in[5];
    const float* b_hh   = (const float*)d_in[6];
    float* out = (float*)d_out;

    __half *glu, *y, *h0, *h1, *wihp, *whhp, *convwr;
    short *z;
    float *c, *bsum;
    cudaGetSymbolAddress((void**)&glu,    g_glu);
    cudaGetSymbolAddress((void**)&y,      g_y);
    cudaGetSymbolAddress((void**)&z,      g_z);
    cudaGetSymbolAddress((void**)&h0,     g_h0);
    cudaGetSymbolAddress((void**)&h1,     g_h1);
    cudaGetSymbolAddress((void**)&c,      g_c);
    cudaGetSymbolAddress((void**)&wihp,   g_wih_p);
    cudaGetSymbolAddress((void**)&whhp,   g_whh_p);
    cudaGetSymbolAddress((void**)&convwr, g_convw_r);
    cudaGetSymbolAddress((void**)&bsum,   g_bsum);

    static int smem_set = 0;
    if (!smem_set) {
        cudaFuncSetAttribute(gemm_mma, cudaFuncAttributeMaxDynamicSharedMemorySize, GEMM_SMEM);
        smem_set = 1;
    }

    // 0. merged weight prep
    prep_kernel<<<(PREP_TOTAL + 255) / 256, 256>>>(
        w_ih, w_hh, conv_w, b_ih, b_hh, wihp, whhp, convwr, bsum);

    // 1. GLU -> fp16
    glu_kernel<<<(S_ROWS * D_HALF / 4 + 255) / 256, 256>>>(x, glu);

    // 2. conv projection: y = glu @ conv_w^T + conv_b (8192x512, K=256) -> fp16
    gemm_mma<<<dim3(D_MODEL / 128, S_ROWS / 128), 256, GEMM_SMEM>>>(
        glu, convwr, y, D_MODEL, D_HALF, conv_b, 1,
        nullptr, nullptr, nullptr, nullptr, nullptr, nullptr, 0, 0);

    // 3. z = y @ w_ih_p^T + bsum (8192x2048, K=512, gate-interleaved) -> int16
    gemm_mma<<<dim3(G4 / 128, S_ROWS / 128), 256, GEMM_SMEM>>>(
        y, wihp, z, G4, D_MODEL, bsum, 2,
        nullptr, nullptr, nullptr, nullptr, nullptr, nullptr, 0, 0);

    // 4. step 0 pointwise (h = c = 0) -> h0
    lstm_step0<<<(S_ROWS * D_MODEL + 255) / 256, 256>>>(z, bsum, c, h0);

    // 5. steps 1..8: fused recurrent GEMM + LSTM cell, ping-pong h buffers
    __half* hb[2] = {h0, h1};
    for (int k = 1; k <= 8; k++) {
        const __half* h_in = hb[(k - 1) & 1];
        __half* hh = (k == 8) ? nullptr : hb[k & 1];
        float*  hf = (k == 8) ? out : nullptr;
        gemm_mma<<<dim3(G4 / 128, S_ROWS / 128), 256, GEMM_SMEM>>>(
            h_in, whhp, nullptr, G4, D_MODEL, nullptr, 0,
            z, bsum, c, c, hh, hf, k, (k < 8) ? 1 : 0);
    }
}